// round 11
// baseline (speedup 1.0000x reference)
#include <cuda_runtime.h>
#include <cuda_fp16.h>
#include <float.h>
#include <stdint.h>

// loss = mean_i [ logsumexp_j t(i,j) - t(i,i) ],  t(i,j) = x_i.y_j - 0.5|y_j|^2
// K=8192, D=128. f16 mma.sync m16n8k16 at its SM-level issue floor
// (~4096 cyc per 128x128x128 tile), log2-domain direct sum-of-exp2 (fp32
// range covers t' in [-170,-20] with >60 octaves margin). Persistent 148
// CTAs; distributed in-kernel finalize via per-CTA completion flags
// (no extra kernel, no device-wide barrier). Exact fp32 diagonal.

#define DD      128
#define KTOT    8192
#define BM      128
#define TN      128
#define YSTRIDE 272                // bytes per smem row (128 f16 + 8 pad)
#define NUNITS  1024               // (8192/128 rb) * (8192/512 cc)
#define NCTA    148
#define LOG2E   1.4426950408889634f
#define LN2     0.6931471805599453f

__device__ __half g_xb[KTOT * DD];      // x * log2e, f16
__device__ __half g_yb[KTOT * DD];      // y, f16
__device__ float  g_ysq[KTOT];          // 0.5*log2e*|y|^2
__device__ float  g_diag[KTOT];         // exact t(i,i), natural units
__device__ float  g_s[NUNITS * BM];     // per-unit row sum of 2^t'
__device__ float  g_rbsum[64];          // per-rowblock loss partial
__device__ unsigned g_cta_flag[NCTA];   // CTA completion flags
__device__ unsigned g_rb_done;          // finalize arrival counter

// ---------------------------------------------------------------------------
__device__ __forceinline__ uint32_t s2u(const void* p) {
    uint32_t a;
    asm("{ .reg .u64 t; cvta.to.shared.u64 t, %1; cvt.u32.u64 %0, t; }"
        : "=r"(a) : "l"(p));
    return a;
}
__device__ __forceinline__ void cp16(uint32_t dst, const void* src) {
    asm volatile("cp.async.cg.shared.global [%0], [%1], 16;"
                 :: "r"(dst), "l"(src) : "memory");
}
__device__ __forceinline__ void ldsm4(uint32_t& r0, uint32_t& r1,
                                      uint32_t& r2, uint32_t& r3, uint32_t a) {
    asm volatile("ldmatrix.sync.aligned.m8n8.x4.shared.b16 {%0,%1,%2,%3}, [%4];"
                 : "=r"(r0), "=r"(r1), "=r"(r2), "=r"(r3) : "r"(a));
}
__device__ __forceinline__ void mma_h(uint32_t* d, const uint32_t* a,
                                      uint32_t b0, uint32_t b1) {
    asm volatile(
        "mma.sync.aligned.m16n8k16.row.col.f16.f16.f16.f16 "
        "{%0,%1}, {%2,%3,%4,%5}, {%6,%7}, {%0,%1};"
        : "+r"(d[0]), "+r"(d[1])
        : "r"(a[0]), "r"(a[1]), "r"(a[2]), "r"(a[3]), "r"(b0), "r"(b1));
}
__device__ __forceinline__ float ex2(float x) {
    float r;
    asm("ex2.approx.ftz.f32 %0, %1;" : "=f"(r) : "f"(x));
    return r;
}
__device__ __forceinline__ float lg2(float x) {
    float r;
    asm("lg2.approx.ftz.f32 %0, %1;" : "=f"(r) : "f"(x));
    return r;
}

// ---------------------------------------------------------------------------
// Prep: f16 conversion (+log2e on X), scaled ysq, exact fp32 diagonal.
// FOUR rows per warp: 8 front-batched float4 loads for deep read MLP.
// ---------------------------------------------------------------------------
__global__ void prep_kernel(const float* __restrict__ X, const float* __restrict__ Y) {
    const int w    = (blockIdx.x * blockDim.x + threadIdx.x) >> 5;  // 0..2047
    const int lane = threadIdx.x & 31;
    const int r    = 4 * w;

    float4 xv[4], yv[4];
    #pragma unroll
    for (int i = 0; i < 4; i++)
        xv[i] = ((const float4*)(X + (size_t)(r + i) * DD))[lane];
    #pragma unroll
    for (int i = 0; i < 4; i++)
        yv[i] = ((const float4*)(Y + (size_t)(r + i) * DD))[lane];

    float d[4], q[4];
    #pragma unroll
    for (int i = 0; i < 4; i++) {
        d[i] = xv[i].x * yv[i].x + xv[i].y * yv[i].y
             + xv[i].z * yv[i].z + xv[i].w * yv[i].w;
        q[i] = yv[i].x * yv[i].x + yv[i].y * yv[i].y
             + yv[i].z * yv[i].z + yv[i].w * yv[i].w;
    }
    #pragma unroll
    for (int off = 16; off; off >>= 1) {
        #pragma unroll
        for (int i = 0; i < 4; i++) {
            d[i] += __shfl_xor_sync(0xffffffffu, d[i], off);
            q[i] += __shfl_xor_sync(0xffffffffu, q[i], off);
        }
    }

    #pragma unroll
    for (int i = 0; i < 4; i++) {
        __half2 xa = __float22half2_rn(make_float2(xv[i].x * LOG2E, xv[i].y * LOG2E));
        __half2 xb = __float22half2_rn(make_float2(xv[i].z * LOG2E, xv[i].w * LOG2E));
        __half2 ya = __float22half2_rn(make_float2(yv[i].x, yv[i].y));
        __half2 yb = __float22half2_rn(make_float2(yv[i].z, yv[i].w));
        uint2 p;
        p.x = *(const unsigned*)&xa;  p.y = *(const unsigned*)&xb;
        ((uint2*)(g_xb + (size_t)(r + i) * DD))[lane] = p;
        p.x = *(const unsigned*)&ya;  p.y = *(const unsigned*)&yb;
        ((uint2*)(g_yb + (size_t)(r + i) * DD))[lane] = p;
    }
    if (lane == 0) {
        #pragma unroll
        for (int i = 0; i < 4; i++) {
            g_ysq[r + i]  = 0.5f * LOG2E * q[i];
            g_diag[r + i] = d[i] - 0.5f * q[i];
        }
    }
}

// ---------------------------------------------------------------------------
// Main: persistent CTAs, f16 HMMA + direct sum-of-exp2, then distributed
// finalize (CTA b<64 finalizes rowblock b after spinning on owner flags).
// 256 threads = 8 warps in 4(m) x 2(n); warp tile 32x64.
// Global tile g in [0,4096): rb = g>>6, col = (g&63)*128, unit = g>>2.
// ---------------------------------------------------------------------------
__global__ __launch_bounds__(256)
void infonce_mma_kernel(float* __restrict__ out) {
    extern __shared__ char dsm[];
    __shared__ float sh[2][BM];
    __shared__ float redf[8];

    const int tid  = threadIdx.x;
    const int wid  = tid >> 5;
    const int lane = tid & 31;

    const uint32_t base = s2u(dsm);
    const uint32_t xsb[2] = {base, base + 34816u};
    const uint32_t ysb[2] = {base + 69632u, base + 104448u};
    const uint32_t yqb[2] = {base + 139264u, base + 139776u};

    const int u0 = (blockIdx.x * NUNITS) / NCTA;
    const int u1 = ((blockIdx.x + 1) * NUNITS) / NCTA;
    const int gbeg = u0 * 4, gend = u1 * 4;

    const int mo = (wid >> 1) * 32;
    const int no = (wid & 1) * 64;
    const uint32_t arow = (uint32_t)(mo + (lane & 15));
    const uint32_t acol = (uint32_t)(lane >> 4) * 16u;
    const uint32_t brow = (uint32_t)(no + ((lane >> 4) & 1) * 8 + (lane & 7));
    const uint32_t bkof = (uint32_t)((lane >> 3) & 1) * 16u;
    const int tg = lane & 3;

    // ---- prologue: X(rb0) + Y(gbeg) + ysq(gbeg), one commit group ----
    {
        const int rb0 = gbeg >> 6, col = (gbeg & 63) * TN;
        const __half* xg = g_xb + (size_t)rb0 * BM * DD;
        const __half* yg = g_yb + (size_t)col * DD;
        #pragma unroll
        for (int i = 0; i < 8; i++) {
            int c = i * 256 + tid;
            int r = c >> 4, kc = c & 15;
            cp16(xsb[0] + r * YSTRIDE + kc * 16, xg + r * DD + kc * 8);
            cp16(ysb[gbeg & 1] + r * YSTRIDE + kc * 16, yg + r * DD + kc * 8);
        }
        if (tid < 32) cp16(yqb[gbeg & 1] + tid * 16, g_ysq + col + tid * 4);
        asm volatile("cp.async.commit_group;" ::: "memory");
    }

    uint32_t afrag[2][8][4];
    int rb_prev = -1, xb = 0;
    float s_run[4];
    #pragma unroll
    for (int i = 0; i < 4; i++) s_run[i] = 0.f;

    #pragma unroll 1
    for (int g = gbeg; g < gend; g++) {
        const int rb = g >> 6;

        // ---- prefetch g+1 (Y always; X when crossing a row block) ----
        if (g + 1 < gend) {
            const int g2 = g + 1, col2 = (g2 & 63) * TN, rb2 = g2 >> 6;
            const __half* yg = g_yb + (size_t)col2 * DD;
            #pragma unroll
            for (int i = 0; i < 8; i++) {
                int c = i * 256 + tid;
                int r = c >> 4, kc = c & 15;
                cp16(ysb[g2 & 1] + r * YSTRIDE + kc * 16, yg + r * DD + kc * 8);
            }
            if (tid < 32) cp16(yqb[g2 & 1] + tid * 16, g_ysq + col2 + tid * 4);
            if (rb2 != rb) {
                const __half* xg = g_xb + (size_t)rb2 * BM * DD;
                #pragma unroll
                for (int i = 0; i < 8; i++) {
                    int c = i * 256 + tid;
                    int r = c >> 4, kc = c & 15;
                    cp16(xsb[xb ^ 1] + r * YSTRIDE + kc * 16, xg + r * DD + kc * 8);
                }
            }
            asm volatile("cp.async.commit_group;" ::: "memory");
            asm volatile("cp.async.wait_group 1;" ::: "memory");
        } else {
            asm volatile("cp.async.wait_group 0;" ::: "memory");
        }
        __syncthreads();

        // ---- (re)load A fragments on row-block change ----
        if (rb != rb_prev) {
            if (rb_prev >= 0) xb ^= 1;
            #pragma unroll
            for (int mt = 0; mt < 2; mt++)
                #pragma unroll
                for (int kt = 0; kt < 8; kt++)
                    ldsm4(afrag[mt][kt][0], afrag[mt][kt][1],
                          afrag[mt][kt][2], afrag[mt][kt][3],
                          xsb[xb] + (arow + mt * 16u) * YSTRIDE + kt * 32u + acol);
            rb_prev = rb;
        }

        // ---- GEMM tile (f16 accum) ----
        const uint32_t yb = ysb[g & 1];
        uint32_t acc[2][8][2];
        #pragma unroll
        for (int mt = 0; mt < 2; mt++)
            #pragma unroll
            for (int nt = 0; nt < 8; nt++) { acc[mt][nt][0] = 0u; acc[mt][nt][1] = 0u; }

        #pragma unroll
        for (int kt = 0; kt < 8; kt++) {
            #pragma unroll
            for (int np = 0; np < 4; np++) {
                uint32_t b0, b1, b2, b3;
                ldsm4(b0, b1, b2, b3,
                      yb + (brow + np * 16u) * YSTRIDE + kt * 32u + bkof);
                mma_h(acc[0][2 * np],     afrag[0][kt], b0, b1);
                mma_h(acc[1][2 * np],     afrag[1][kt], b0, b1);
                mma_h(acc[0][2 * np + 1], afrag[0][kt], b2, b3);
                mma_h(acc[1][2 * np + 1], afrag[1][kt], b2, b3);
            }
        }

        // ---- epilogue: direct sum of 2^(t') — no max, no rescale ----
        const float* ysqp = (const float*)(dsm + 139264 + (g & 1) * 512);
        float2 yq[8];
        #pragma unroll
        for (int nt = 0; nt < 8; nt++)
            yq[nt] = *(const float2*)(ysqp + no + nt * 8 + 2 * tg);

        #pragma unroll
        for (int ri = 0; ri < 4; ri++) {
            const int mt = ri >> 1, hi = ri & 1;
            float cs0 = 0.f, cs1 = 0.f;
            #pragma unroll
            for (int nt = 0; nt < 8; nt++) {
                __half2 h = *reinterpret_cast<__half2*>(&acc[mt][nt][hi]);
                float2 f = __half22float2(h);
                cs0 += ex2(f.x - yq[nt].x);
                cs1 += ex2(f.y - yq[nt].y);
            }
            s_run[ri] += cs0 + cs1;
        }

        // ---- unit boundary: quad-add, merge n-halves, flush, reset ----
        if ((g & 3) == 3) {
            const int u = g >> 2;
            #pragma unroll
            for (int ri = 0; ri < 4; ri++) {
                s_run[ri] += __shfl_xor_sync(0xffffffffu, s_run[ri], 1);
                s_run[ri] += __shfl_xor_sync(0xffffffffu, s_run[ri], 2);
            }
            if ((lane & 3) == 0) {
                const int gq = lane >> 2;
                #pragma unroll
                for (int ri = 0; ri < 4; ri++) {
                    int rowl = mo + gq + (ri & 1) * 8 + (ri >> 1) * 16;
                    sh[wid & 1][rowl] = s_run[ri];
                }
            }
            __syncthreads();
            if (tid < BM)
                g_s[u * BM + tid] = sh[0][tid] + sh[1][tid];
            #pragma unroll
            for (int i = 0; i < 4; i++) s_run[i] = 0.f;
        }
    }

    // ============== distributed finalize (no barrier, no extra kernel) =====
    // Publish completion: fence the g_s stores, then raise this CTA's flag.
    if (tid < BM) __threadfence();
    __syncthreads();
    if (tid == 0)
        ((volatile unsigned*)g_cta_flag)[blockIdx.x] = 1u;

    if (blockIdx.x < 64) {
        const int rb = blockIdx.x;
        // owner CTA of unit u: ((u+1)*NCTA - 1) / NUNITS
        const int olo = ((rb * 16 + 1) * NCTA - 1) / NUNITS;
        const int ohi = ((rb * 16 + 16) * NCTA - 1) / NUNITS;
        if (tid == 0) {
            for (int c = olo; c <= ohi; c++)
                while (((volatile unsigned*)g_cta_flag)[c] == 0u) { }
        }
        __syncthreads();
        __threadfence();   // acquire: owners' g_s stores now visible

        float v = 0.f;
        if (tid < BM) {
            const int row = rb * BM + tid;
            float S = 0.f;
            #pragma unroll
            for (int cc = 0; cc < 16; cc++)
                S += g_s[(rb * 16 + cc) * BM + tid];
            v = LN2 * lg2(S) - g_diag[row];
        }
        #pragma unroll
        for (int off = 16; off; off >>= 1)
            v += __shfl_xor_sync(0xffffffffu, v, off);
        if (lane == 0) redf[wid] = v;
        __syncthreads();
        if (tid == 0) {
            float t = 0.f;
            #pragma unroll
            for (int k = 0; k < 8; k++) t += redf[k];
            g_rbsum[rb] = t;
            __threadfence();
            unsigned dc = atomicAdd(&g_rb_done, 1u);
            if (dc == 63u) {               // all 64 rowblocks finalized
                __threadfence();
                float tot = 0.f;
                #pragma unroll
                for (int k = 0; k < 64; k++)
                    tot += ((volatile float*)g_rbsum)[k];
                out[0] = tot * (1.0f / (float)KTOT);
                // reset for next graph replay (all flag setters are done)
                g_rb_done = 0u;
                for (int c = 0; c < NCTA; c++)
                    ((volatile unsigned*)g_cta_flag)[c] = 0u;
            }
        }
    }
}

// ---------------------------------------------------------------------------
extern "C" void kernel_launch(void* const* d_in, const int* in_sizes, int n_in,
                              void* d_out, int out_size) {
    const float* X = (const float*)d_in[0];  // features_nc
    const float* Y = (const float*)d_in[1];  // features_c

    const size_t dsmem = 140288;  // 2*X + 2*Y + 2*ysq
    cudaFuncSetAttribute(infonce_mma_kernel,
                         cudaFuncAttributeMaxDynamicSharedMemorySize, (int)dsmem);

    prep_kernel<<<256, 256>>>(X, Y);
    infonce_mma_kernel<<<NCTA, 256, dsmem>>>((float*)d_out);
}

// round 12
// speedup vs baseline: 1.0562x; 1.0562x over previous
#include <cuda_runtime.h>
#include <cuda_fp16.h>
#include <float.h>
#include <stdint.h>

// loss = mean_i [ logsumexp_j t(i,j) - t(i,i) ],  t(i,j) = x_i.y_j - 0.5|y_j|^2
// K=8192, D=128. f16 mma.sync m16n8k16 at its SM-level issue floor
// (~4096 cyc per 128x128x128 tile), log2-domain direct sum-of-exp2 (fp32
// range covers t' in [-170,-20] with >60 octaves of margin). Persistent 148
// CTAs. 4-row-per-warp prep (deep LDG MLP). Separate tiny finalize kernel.
// Exact fp32 diagonal.

#define DD      128
#define KTOT    8192
#define BM      128
#define TN      128
#define YSTRIDE 272                // bytes per smem row (128 f16 + 8 pad)
#define NUNITS  1024               // (8192/128 rb) * (8192/512 cc)
#define NCTA    148
#define LOG2E   1.4426950408889634f
#define LN2     0.6931471805599453f

__device__ __half g_xb[KTOT * DD];      // x * log2e, f16
__device__ __half g_yb[KTOT * DD];      // y, f16
__device__ float  g_ysq[KTOT];          // 0.5*log2e*|y|^2
__device__ float  g_diag[KTOT];         // exact t(i,i), natural units
__device__ float  g_s[NUNITS * BM];     // per-unit row sum of 2^t'
__device__ float  g_partial[32];
__device__ unsigned g_done;

// ---------------------------------------------------------------------------
__device__ __forceinline__ uint32_t s2u(const void* p) {
    uint32_t a;
    asm("{ .reg .u64 t; cvta.to.shared.u64 t, %1; cvt.u32.u64 %0, t; }"
        : "=r"(a) : "l"(p));
    return a;
}
__device__ __forceinline__ void cp16(uint32_t dst, const void* src) {
    asm volatile("cp.async.cg.shared.global [%0], [%1], 16;"
                 :: "r"(dst), "l"(src) : "memory");
}
__device__ __forceinline__ void ldsm4(uint32_t& r0, uint32_t& r1,
                                      uint32_t& r2, uint32_t& r3, uint32_t a) {
    asm volatile("ldmatrix.sync.aligned.m8n8.x4.shared.b16 {%0,%1,%2,%3}, [%4];"
                 : "=r"(r0), "=r"(r1), "=r"(r2), "=r"(r3) : "r"(a));
}
__device__ __forceinline__ void mma_h(uint32_t* d, const uint32_t* a,
                                      uint32_t b0, uint32_t b1) {
    asm volatile(
        "mma.sync.aligned.m16n8k16.row.col.f16.f16.f16.f16 "
        "{%0,%1}, {%2,%3,%4,%5}, {%6,%7}, {%0,%1};"
        : "+r"(d[0]), "+r"(d[1])
        : "r"(a[0]), "r"(a[1]), "r"(a[2]), "r"(a[3]), "r"(b0), "r"(b1));
}
__device__ __forceinline__ float ex2(float x) {
    float r;
    asm("ex2.approx.ftz.f32 %0, %1;" : "=f"(r) : "f"(x));
    return r;
}
__device__ __forceinline__ float lg2(float x) {
    float r;
    asm("lg2.approx.ftz.f32 %0, %1;" : "=f"(r) : "f"(x));
    return r;
}

// ---------------------------------------------------------------------------
// Prep: f16 conversion (+log2e on X), scaled ysq, exact fp32 diagonal.
// FOUR rows per warp: 8 front-batched float4 loads for deep read MLP.
// ---------------------------------------------------------------------------
__global__ void prep_kernel(const float* __restrict__ X, const float* __restrict__ Y) {
    if (blockIdx.x == 0 && threadIdx.x == 0) g_done = 0u;
    const int w    = (blockIdx.x * blockDim.x + threadIdx.x) >> 5;  // 0..2047
    const int lane = threadIdx.x & 31;
    const int r    = 4 * w;

    float4 xv[4], yv[4];
    #pragma unroll
    for (int i = 0; i < 4; i++)
        xv[i] = ((const float4*)(X + (size_t)(r + i) * DD))[lane];
    #pragma unroll
    for (int i = 0; i < 4; i++)
        yv[i] = ((const float4*)(Y + (size_t)(r + i) * DD))[lane];

    float d[4], q[4];
    #pragma unroll
    for (int i = 0; i < 4; i++) {
        d[i] = xv[i].x * yv[i].x + xv[i].y * yv[i].y
             + xv[i].z * yv[i].z + xv[i].w * yv[i].w;
        q[i] = yv[i].x * yv[i].x + yv[i].y * yv[i].y
             + yv[i].z * yv[i].z + yv[i].w * yv[i].w;
    }
    #pragma unroll
    for (int off = 16; off; off >>= 1) {
        #pragma unroll
        for (int i = 0; i < 4; i++) {
            d[i] += __shfl_xor_sync(0xffffffffu, d[i], off);
            q[i] += __shfl_xor_sync(0xffffffffu, q[i], off);
        }
    }

    #pragma unroll
    for (int i = 0; i < 4; i++) {
        __half2 xa = __float22half2_rn(make_float2(xv[i].x * LOG2E, xv[i].y * LOG2E));
        __half2 xb = __float22half2_rn(make_float2(xv[i].z * LOG2E, xv[i].w * LOG2E));
        __half2 ya = __float22half2_rn(make_float2(yv[i].x, yv[i].y));
        __half2 yb = __float22half2_rn(make_float2(yv[i].z, yv[i].w));
        uint2 p;
        p.x = *(const unsigned*)&xa;  p.y = *(const unsigned*)&xb;
        ((uint2*)(g_xb + (size_t)(r + i) * DD))[lane] = p;
        p.x = *(const unsigned*)&ya;  p.y = *(const unsigned*)&yb;
        ((uint2*)(g_yb + (size_t)(r + i) * DD))[lane] = p;
    }
    if (lane == 0) {
        #pragma unroll
        for (int i = 0; i < 4; i++) {
            g_ysq[r + i]  = 0.5f * LOG2E * q[i];
            g_diag[r + i] = d[i] - 0.5f * q[i];
        }
    }
}

// ---------------------------------------------------------------------------
// Main: persistent CTAs, f16 HMMA + direct sum-of-exp2 (no max tracking).
// 256 threads = 8 warps in 4(m) x 2(n); warp tile 32x64.
// Global tile g in [0,4096): rb = g>>6, col = (g&63)*128, unit = g>>2.
// ---------------------------------------------------------------------------
__global__ __launch_bounds__(256)
void infonce_mma_kernel() {
    extern __shared__ char dsm[];
    __shared__ float sh[2][BM];

    const int tid  = threadIdx.x;
    const int wid  = tid >> 5;
    const int lane = tid & 31;

    const uint32_t base = s2u(dsm);
    const uint32_t xsb[2] = {base, base + 34816u};
    const uint32_t ysb[2] = {base + 69632u, base + 104448u};
    const uint32_t yqb[2] = {base + 139264u, base + 139776u};

    const int u0 = (blockIdx.x * NUNITS) / NCTA;
    const int u1 = ((blockIdx.x + 1) * NUNITS) / NCTA;
    const int gbeg = u0 * 4, gend = u1 * 4;

    const int mo = (wid >> 1) * 32;
    const int no = (wid & 1) * 64;
    const uint32_t arow = (uint32_t)(mo + (lane & 15));
    const uint32_t acol = (uint32_t)(lane >> 4) * 16u;
    const uint32_t brow = (uint32_t)(no + ((lane >> 4) & 1) * 8 + (lane & 7));
    const uint32_t bkof = (uint32_t)((lane >> 3) & 1) * 16u;
    const int tg = lane & 3;

    // ---- prologue: X(rb0) + Y(gbeg) + ysq(gbeg), one commit group ----
    {
        const int rb0 = gbeg >> 6, col = (gbeg & 63) * TN;
        const __half* xg = g_xb + (size_t)rb0 * BM * DD;
        const __half* yg = g_yb + (size_t)col * DD;
        #pragma unroll
        for (int i = 0; i < 8; i++) {
            int c = i * 256 + tid;
            int r = c >> 4, kc = c & 15;
            cp16(xsb[0] + r * YSTRIDE + kc * 16, xg + r * DD + kc * 8);
            cp16(ysb[gbeg & 1] + r * YSTRIDE + kc * 16, yg + r * DD + kc * 8);
        }
        if (tid < 32) cp16(yqb[gbeg & 1] + tid * 16, g_ysq + col + tid * 4);
        asm volatile("cp.async.commit_group;" ::: "memory");
    }

    uint32_t afrag[2][8][4];
    int rb_prev = -1, xb = 0;
    float s_run[4];
    #pragma unroll
    for (int i = 0; i < 4; i++) s_run[i] = 0.f;

    #pragma unroll 1
    for (int g = gbeg; g < gend; g++) {
        const int rb = g >> 6;

        // ---- prefetch g+1 (Y always; X when crossing a row block) ----
        if (g + 1 < gend) {
            const int g2 = g + 1, col2 = (g2 & 63) * TN, rb2 = g2 >> 6;
            const __half* yg = g_yb + (size_t)col2 * DD;
            #pragma unroll
            for (int i = 0; i < 8; i++) {
                int c = i * 256 + tid;
                int r = c >> 4, kc = c & 15;
                cp16(ysb[g2 & 1] + r * YSTRIDE + kc * 16, yg + r * DD + kc * 8);
            }
            if (tid < 32) cp16(yqb[g2 & 1] + tid * 16, g_ysq + col2 + tid * 4);
            if (rb2 != rb) {
                const __half* xg = g_xb + (size_t)rb2 * BM * DD;
                #pragma unroll
                for (int i = 0; i < 8; i++) {
                    int c = i * 256 + tid;
                    int r = c >> 4, kc = c & 15;
                    cp16(xsb[xb ^ 1] + r * YSTRIDE + kc * 16, xg + r * DD + kc * 8);
                }
            }
            asm volatile("cp.async.commit_group;" ::: "memory");
            asm volatile("cp.async.wait_group 1;" ::: "memory");
        } else {
            asm volatile("cp.async.wait_group 0;" ::: "memory");
        }
        __syncthreads();

        // ---- (re)load A fragments on row-block change ----
        if (rb != rb_prev) {
            if (rb_prev >= 0) xb ^= 1;
            #pragma unroll
            for (int mt = 0; mt < 2; mt++)
                #pragma unroll
                for (int kt = 0; kt < 8; kt++)
                    ldsm4(afrag[mt][kt][0], afrag[mt][kt][1],
                          afrag[mt][kt][2], afrag[mt][kt][3],
                          xsb[xb] + (arow + mt * 16u) * YSTRIDE + kt * 32u + acol);
            rb_prev = rb;
        }

        // ---- GEMM tile (f16 accum) ----
        const uint32_t yb = ysb[g & 1];
        uint32_t acc[2][8][2];
        #pragma unroll
        for (int mt = 0; mt < 2; mt++)
            #pragma unroll
            for (int nt = 0; nt < 8; nt++) { acc[mt][nt][0] = 0u; acc[mt][nt][1] = 0u; }

        #pragma unroll
        for (int kt = 0; kt < 8; kt++) {
            #pragma unroll
            for (int np = 0; np < 4; np++) {
                uint32_t b0, b1, b2, b3;
                ldsm4(b0, b1, b2, b3,
                      yb + (brow + np * 16u) * YSTRIDE + kt * 32u + bkof);
                mma_h(acc[0][2 * np],     afrag[0][kt], b0, b1);
                mma_h(acc[1][2 * np],     afrag[1][kt], b0, b1);
                mma_h(acc[0][2 * np + 1], afrag[0][kt], b2, b3);
                mma_h(acc[1][2 * np + 1], afrag[1][kt], b2, b3);
            }
        }

        // ---- epilogue: direct sum of 2^(t') — no max, no rescale ----
        const float* ysqp = (const float*)(dsm + 139264 + (g & 1) * 512);
        float2 yq[8];
        #pragma unroll
        for (int nt = 0; nt < 8; nt++)
            yq[nt] = *(const float2*)(ysqp + no + nt * 8 + 2 * tg);

        #pragma unroll
        for (int ri = 0; ri < 4; ri++) {
            const int mt = ri >> 1, hi = ri & 1;
            float cs0 = 0.f, cs1 = 0.f;
            #pragma unroll
            for (int nt = 0; nt < 8; nt++) {
                __half2 h = *reinterpret_cast<__half2*>(&acc[mt][nt][hi]);
                float2 f = __half22float2(h);
                cs0 += ex2(f.x - yq[nt].x);
                cs1 += ex2(f.y - yq[nt].y);
            }
            s_run[ri] += cs0 + cs1;
        }

        // ---- unit boundary: quad-add, merge n-halves, flush, reset ----
        if ((g & 3) == 3) {
            const int u = g >> 2;
            #pragma unroll
            for (int ri = 0; ri < 4; ri++) {
                s_run[ri] += __shfl_xor_sync(0xffffffffu, s_run[ri], 1);
                s_run[ri] += __shfl_xor_sync(0xffffffffu, s_run[ri], 2);
            }
            if ((lane & 3) == 0) {
                const int gq = lane >> 2;
                #pragma unroll
                for (int ri = 0; ri < 4; ri++) {
                    int rowl = mo + gq + (ri & 1) * 8 + (ri >> 1) * 16;
                    sh[wid & 1][rowl] = s_run[ri];
                }
            }
            __syncthreads();
            if (tid < BM)
                g_s[u * BM + tid] = sh[0][tid] + sh[1][tid];
            #pragma unroll
            for (int i = 0; i < 4; i++) s_run[i] = 0.f;
        }
    }
}

// ---------------------------------------------------------------------------
// Finalize: per-row sum of 16 column-unit partials; last block reduces all.
// ---------------------------------------------------------------------------
__global__ void finalize_kernel(float* __restrict__ out) {
    __shared__ float red[8];
    __shared__ bool last;
    const int tid = threadIdx.x;                 // 256
    const int row = blockIdx.x * 256 + tid;
    const int rb = row >> 7, rl = row & 127;

    float S = 0.f;
    #pragma unroll
    for (int cc = 0; cc < 16; cc++)
        S += g_s[(rb * 16 + cc) * BM + rl];

    float v = LN2 * lg2(S) - g_diag[row];
    #pragma unroll
    for (int off = 16; off; off >>= 1)
        v += __shfl_xor_sync(0xffffffffu, v, off);
    if ((tid & 31) == 0) red[tid >> 5] = v;
    __syncthreads();
    if (tid == 0) {
        float t = 0.f;
        #pragma unroll
        for (int k = 0; k < 8; k++) t += red[k];
        g_partial[blockIdx.x] = t;
        __threadfence();
        unsigned old = atomicAdd(&g_done, 1u);
        last = (old == 31u);
    }
    __syncthreads();
    if (last && tid == 0) {
        float tot = 0.f;
        #pragma unroll
        for (int k = 0; k < 32; k++)
            tot += ((volatile float*)g_partial)[k];
        out[0] = tot * (1.0f / (float)KTOT);
    }
}

// ---------------------------------------------------------------------------
extern "C" void kernel_launch(void* const* d_in, const int* in_sizes, int n_in,
                              void* d_out, int out_size) {
    const float* X = (const float*)d_in[0];  // features_nc
    const float* Y = (const float*)d_in[1];  // features_c

    const size_t dsmem = 140288;  // 2*X + 2*Y + 2*ysq
    cudaFuncSetAttribute(infonce_mma_kernel,
                         cudaFuncAttributeMaxDynamicSharedMemorySize, (int)dsmem);

    prep_kernel<<<256, 256>>>(X, Y);
    infonce_mma_kernel<<<NCTA, 256, dsmem>>>();
    finalize_kernel<<<32, 256>>>((float*)d_out);
}

// round 13
// speedup vs baseline: 1.0895x; 1.0315x over previous
#include <cuda_runtime.h>
#include <cuda_fp16.h>
#include <float.h>
#include <stdint.h>

// loss = mean_i [ logsumexp_j t(i,j) - t(i,i) ],  t(i,j) = x_i.y_j - 0.5|y_j|^2
// K=8192, D=128. f16 mma.sync m16n8k16 at the sm_103 legacy-HMMA HW cap
// (512 MAC/cyc/SM -> 4096 cyc per 128x128x128 tile), log2-domain direct
// sum-of-exp2 (fp32 covers t' in [-170,-20] with >60 octaves margin).
// Persistent 148 CTAs. PDL chains prep->main->finalize to hide launch ramps.
// Exact fp32 diagonal.

#define DD      128
#define KTOT    8192
#define BM      128
#define TN      128
#define YSTRIDE 272                // bytes per smem row (128 f16 + 8 pad)
#define NUNITS  1024               // (8192/128 rb) * (8192/512 cc)
#define NCTA    148
#define LOG2E   1.4426950408889634f
#define LN2     0.6931471805599453f

__device__ __half g_xb[KTOT * DD];      // x * log2e, f16
__device__ __half g_yb[KTOT * DD];      // y, f16
__device__ float  g_ysq[KTOT];          // 0.5*log2e*|y|^2
__device__ float  g_diag[KTOT];         // exact t(i,i), natural units
__device__ float  g_s[NUNITS * BM];     // per-unit row sum of 2^t'
__device__ float  g_partial[32];
__device__ unsigned g_done;

// ---------------------------------------------------------------------------
__device__ __forceinline__ uint32_t s2u(const void* p) {
    uint32_t a;
    asm("{ .reg .u64 t; cvta.to.shared.u64 t, %1; cvt.u32.u64 %0, t; }"
        : "=r"(a) : "l"(p));
    return a;
}
__device__ __forceinline__ void cp16(uint32_t dst, const void* src) {
    asm volatile("cp.async.cg.shared.global [%0], [%1], 16;"
                 :: "r"(dst), "l"(src) : "memory");
}
__device__ __forceinline__ void ldsm4(uint32_t& r0, uint32_t& r1,
                                      uint32_t& r2, uint32_t& r3, uint32_t a) {
    asm volatile("ldmatrix.sync.aligned.m8n8.x4.shared.b16 {%0,%1,%2,%3}, [%4];"
                 : "=r"(r0), "=r"(r1), "=r"(r2), "=r"(r3) : "r"(a));
}
__device__ __forceinline__ void mma_h(uint32_t* d, const uint32_t* a,
                                      uint32_t b0, uint32_t b1) {
    asm volatile(
        "mma.sync.aligned.m16n8k16.row.col.f16.f16.f16.f16 "
        "{%0,%1}, {%2,%3,%4,%5}, {%6,%7}, {%0,%1};"
        : "+r"(d[0]), "+r"(d[1])
        : "r"(a[0]), "r"(a[1]), "r"(a[2]), "r"(a[3]), "r"(b0), "r"(b1));
}
__device__ __forceinline__ float ex2(float x) {
    float r;
    asm("ex2.approx.ftz.f32 %0, %1;" : "=f"(r) : "f"(x));
    return r;
}
__device__ __forceinline__ float lg2(float x) {
    float r;
    asm("lg2.approx.ftz.f32 %0, %1;" : "=f"(r) : "f"(x));
    return r;
}
__device__ __forceinline__ void pdl_trigger() {
    asm volatile("griddepcontrol.launch_dependents;" ::: "memory");
}
__device__ __forceinline__ void pdl_wait() {
    asm volatile("griddepcontrol.wait;" ::: "memory");
}

// ---------------------------------------------------------------------------
// Prep: f16 conversion (+log2e on X), scaled ysq, exact fp32 diagonal.
// FOUR rows per warp: 8 front-batched float4 loads for deep read MLP.
// Triggers dependent (main) launch immediately: all 256 blocks co-resident.
// ---------------------------------------------------------------------------
__global__ void prep_kernel(const float* __restrict__ X, const float* __restrict__ Y) {
    pdl_trigger();
    if (blockIdx.x == 0 && threadIdx.x == 0) g_done = 0u;
    const int w    = (blockIdx.x * blockDim.x + threadIdx.x) >> 5;  // 0..2047
    const int lane = threadIdx.x & 31;
    const int r    = 4 * w;

    float4 xv[4], yv[4];
    #pragma unroll
    for (int i = 0; i < 4; i++)
        xv[i] = ((const float4*)(X + (size_t)(r + i) * DD))[lane];
    #pragma unroll
    for (int i = 0; i < 4; i++)
        yv[i] = ((const float4*)(Y + (size_t)(r + i) * DD))[lane];

    float d[4], q[4];
    #pragma unroll
    for (int i = 0; i < 4; i++) {
        d[i] = xv[i].x * yv[i].x + xv[i].y * yv[i].y
             + xv[i].z * yv[i].z + xv[i].w * yv[i].w;
        q[i] = yv[i].x * yv[i].x + yv[i].y * yv[i].y
             + yv[i].z * yv[i].z + yv[i].w * yv[i].w;
    }
    #pragma unroll
    for (int off = 16; off; off >>= 1) {
        #pragma unroll
        for (int i = 0; i < 4; i++) {
            d[i] += __shfl_xor_sync(0xffffffffu, d[i], off);
            q[i] += __shfl_xor_sync(0xffffffffu, q[i], off);
        }
    }

    #pragma unroll
    for (int i = 0; i < 4; i++) {
        __half2 xa = __float22half2_rn(make_float2(xv[i].x * LOG2E, xv[i].y * LOG2E));
        __half2 xb = __float22half2_rn(make_float2(xv[i].z * LOG2E, xv[i].w * LOG2E));
        __half2 ya = __float22half2_rn(make_float2(yv[i].x, yv[i].y));
        __half2 yb = __float22half2_rn(make_float2(yv[i].z, yv[i].w));
        uint2 p;
        p.x = *(const unsigned*)&xa;  p.y = *(const unsigned*)&xb;
        ((uint2*)(g_xb + (size_t)(r + i) * DD))[lane] = p;
        p.x = *(const unsigned*)&ya;  p.y = *(const unsigned*)&yb;
        ((uint2*)(g_yb + (size_t)(r + i) * DD))[lane] = p;
    }
    if (lane == 0) {
        #pragma unroll
        for (int i = 0; i < 4; i++) {
            g_ysq[r + i]  = 0.5f * LOG2E * q[i];
            g_diag[r + i] = d[i] - 0.5f * q[i];
        }
    }
}

// ---------------------------------------------------------------------------
// Main: persistent CTAs, f16 HMMA + direct sum-of-exp2 (no max tracking).
// 256 threads = 8 warps in 4(m) x 2(n); warp tile 32x64.
// Global tile g in [0,4096): rb = g>>6, col = (g&63)*128, unit = g>>2.
// PDL: waits on prep before first cp.async; triggers finalize launch.
// ---------------------------------------------------------------------------
__global__ __launch_bounds__(256)
void infonce_mma_kernel() {
    extern __shared__ char dsm[];
    __shared__ float sh[2][BM];

    const int tid  = threadIdx.x;
    const int wid  = tid >> 5;
    const int lane = tid & 31;

    const uint32_t base = s2u(dsm);
    const uint32_t xsb[2] = {base, base + 34816u};
    const uint32_t ysb[2] = {base + 69632u, base + 104448u};
    const uint32_t yqb[2] = {base + 139264u, base + 139776u};

    const int u0 = (blockIdx.x * NUNITS) / NCTA;
    const int u1 = ((blockIdx.x + 1) * NUNITS) / NCTA;
    const int gbeg = u0 * 4, gend = u1 * 4;

    const int mo = (wid >> 1) * 32;
    const int no = (wid & 1) * 64;
    const uint32_t arow = (uint32_t)(mo + (lane & 15));
    const uint32_t acol = (uint32_t)(lane >> 4) * 16u;
    const uint32_t brow = (uint32_t)(no + ((lane >> 4) & 1) * 8 + (lane & 7));
    const uint32_t bkof = (uint32_t)((lane >> 3) & 1) * 16u;
    const int tg = lane & 3;

    // wait for prep's memory, then let finalize start launching
    pdl_wait();
    pdl_trigger();

    // ---- prologue: X(rb0) + Y(gbeg) + ysq(gbeg), one commit group ----
    {
        const int rb0 = gbeg >> 6, col = (gbeg & 63) * TN;
        const __half* xg = g_xb + (size_t)rb0 * BM * DD;
        const __half* yg = g_yb + (size_t)col * DD;
        #pragma unroll
        for (int i = 0; i < 8; i++) {
            int c = i * 256 + tid;
            int r = c >> 4, kc = c & 15;
            cp16(xsb[0] + r * YSTRIDE + kc * 16, xg + r * DD + kc * 8);
            cp16(ysb[gbeg & 1] + r * YSTRIDE + kc * 16, yg + r * DD + kc * 8);
        }
        if (tid < 32) cp16(yqb[gbeg & 1] + tid * 16, g_ysq + col + tid * 4);
        asm volatile("cp.async.commit_group;" ::: "memory");
    }

    uint32_t afrag[2][8][4];
    int rb_prev = -1, xb = 0;
    float s_run[4];
    #pragma unroll
    for (int i = 0; i < 4; i++) s_run[i] = 0.f;

    #pragma unroll 1
    for (int g = gbeg; g < gend; g++) {
        const int rb = g >> 6;

        // ---- prefetch g+1 (Y always; X when crossing a row block) ----
        if (g + 1 < gend) {
            const int g2 = g + 1, col2 = (g2 & 63) * TN, rb2 = g2 >> 6;
            const __half* yg = g_yb + (size_t)col2 * DD;
            #pragma unroll
            for (int i = 0; i < 8; i++) {
                int c = i * 256 + tid;
                int r = c >> 4, kc = c & 15;
                cp16(ysb[g2 & 1] + r * YSTRIDE + kc * 16, yg + r * DD + kc * 8);
            }
            if (tid < 32) cp16(yqb[g2 & 1] + tid * 16, g_ysq + col2 + tid * 4);
            if (rb2 != rb) {
                const __half* xg = g_xb + (size_t)rb2 * BM * DD;
                #pragma unroll
                for (int i = 0; i < 8; i++) {
                    int c = i * 256 + tid;
                    int r = c >> 4, kc = c & 15;
                    cp16(xsb[xb ^ 1] + r * YSTRIDE + kc * 16, xg + r * DD + kc * 8);
                }
            }
            asm volatile("cp.async.commit_group;" ::: "memory");
            asm volatile("cp.async.wait_group 1;" ::: "memory");
        } else {
            asm volatile("cp.async.wait_group 0;" ::: "memory");
        }
        __syncthreads();

        // ---- (re)load A fragments on row-block change ----
        if (rb != rb_prev) {
            if (rb_prev >= 0) xb ^= 1;
            #pragma unroll
            for (int mt = 0; mt < 2; mt++)
                #pragma unroll
                for (int kt = 0; kt < 8; kt++)
                    ldsm4(afrag[mt][kt][0], afrag[mt][kt][1],
                          afrag[mt][kt][2], afrag[mt][kt][3],
                          xsb[xb] + (arow + mt * 16u) * YSTRIDE + kt * 32u + acol);
            rb_prev = rb;
        }

        // ---- GEMM tile (f16 accum) ----
        const uint32_t yb = ysb[g & 1];
        uint32_t acc[2][8][2];
        #pragma unroll
        for (int mt = 0; mt < 2; mt++)
            #pragma unroll
            for (int nt = 0; nt < 8; nt++) { acc[mt][nt][0] = 0u; acc[mt][nt][1] = 0u; }

        #pragma unroll
        for (int kt = 0; kt < 8; kt++) {
            #pragma unroll
            for (int np = 0; np < 4; np++) {
                uint32_t b0, b1, b2, b3;
                ldsm4(b0, b1, b2, b3,
                      yb + (brow + np * 16u) * YSTRIDE + kt * 32u + bkof);
                mma_h(acc[0][2 * np],     afrag[0][kt], b0, b1);
                mma_h(acc[1][2 * np],     afrag[1][kt], b0, b1);
                mma_h(acc[0][2 * np + 1], afrag[0][kt], b2, b3);
                mma_h(acc[1][2 * np + 1], afrag[1][kt], b2, b3);
            }
        }

        // ---- epilogue: direct sum of 2^(t') — no max, no rescale ----
        const float* ysqp = (const float*)(dsm + 139264 + (g & 1) * 512);
        float2 yq[8];
        #pragma unroll
        for (int nt = 0; nt < 8; nt++)
            yq[nt] = *(const float2*)(ysqp + no + nt * 8 + 2 * tg);

        #pragma unroll
        for (int ri = 0; ri < 4; ri++) {
            const int mt = ri >> 1, hi = ri & 1;
            float cs0 = 0.f, cs1 = 0.f;
            #pragma unroll
            for (int nt = 0; nt < 8; nt++) {
                __half2 h = *reinterpret_cast<__half2*>(&acc[mt][nt][hi]);
                float2 f = __half22float2(h);
                cs0 += ex2(f.x - yq[nt].x);
                cs1 += ex2(f.y - yq[nt].y);
            }
            s_run[ri] += cs0 + cs1;
        }

        // ---- unit boundary: quad-add, merge n-halves, flush, reset ----
        if ((g & 3) == 3) {
            const int u = g >> 2;
            #pragma unroll
            for (int ri = 0; ri < 4; ri++) {
                s_run[ri] += __shfl_xor_sync(0xffffffffu, s_run[ri], 1);
                s_run[ri] += __shfl_xor_sync(0xffffffffu, s_run[ri], 2);
            }
            if ((lane & 3) == 0) {
                const int gq = lane >> 2;
                #pragma unroll
                for (int ri = 0; ri < 4; ri++) {
                    int rowl = mo + gq + (ri & 1) * 8 + (ri >> 1) * 16;
                    sh[wid & 1][rowl] = s_run[ri];
                }
            }
            __syncthreads();
            if (tid < BM)
                g_s[u * BM + tid] = sh[0][tid] + sh[1][tid];
            #pragma unroll
            for (int i = 0; i < 4; i++) s_run[i] = 0.f;
        }
    }
}

// ---------------------------------------------------------------------------
// Finalize: per-row sum of 16 column-unit partials; last block reduces all.
// PDL: launched early; waits for main's memory before reading g_s.
// ---------------------------------------------------------------------------
__global__ void finalize_kernel(float* __restrict__ out) {
    __shared__ float red[8];
    __shared__ bool last;
    const int tid = threadIdx.x;                 // 256
    const int row = blockIdx.x * 256 + tid;
    const int rb = row >> 7, rl = row & 127;

    pdl_wait();

    float S = 0.f;
    #pragma unroll
    for (int cc = 0; cc < 16; cc++)
        S += g_s[(rb * 16 + cc) * BM + rl];

    float v = LN2 * lg2(S) - g_diag[row];
    #pragma unroll
    for (int off = 16; off; off >>= 1)
        v += __shfl_xor_sync(0xffffffffu, v, off);
    if ((tid & 31) == 0) red[tid >> 5] = v;
    __syncthreads();
    if (tid == 0) {
        float t = 0.f;
        #pragma unroll
        for (int k = 0; k < 8; k++) t += red[k];
        g_partial[blockIdx.x] = t;
        __threadfence();
        unsigned old = atomicAdd(&g_done, 1u);
        last = (old == 31u);
    }
    __syncthreads();
    if (last && tid == 0) {
        float tot = 0.f;
        #pragma unroll
        for (int k = 0; k < 32; k++)
            tot += ((volatile float*)g_partial)[k];
        out[0] = tot * (1.0f / (float)KTOT);
    }
}

// ---------------------------------------------------------------------------
extern "C" void kernel_launch(void* const* d_in, const int* in_sizes, int n_in,
                              void* d_out, int out_size) {
    const float* X = (const float*)d_in[0];  // features_nc
    const float* Y = (const float*)d_in[1];  // features_c

    const size_t dsmem = 140288;  // 2*X + 2*Y + 2*ysq
    cudaFuncSetAttribute(infonce_mma_kernel,
                         cudaFuncAttributeMaxDynamicSharedMemorySize, (int)dsmem);

    // prep (plain launch)
    prep_kernel<<<256, 256>>>(X, Y);

    // main with programmatic dependent launch on prep
    {
        cudaLaunchAttribute attr[1];
        attr[0].id = cudaLaunchAttributeProgrammaticStreamSerialization;
        attr[0].val.programmaticStreamSerializationAllowed = 1;
        cudaLaunchConfig_t cfg = {};
        cfg.gridDim = dim3(NCTA, 1, 1);
        cfg.blockDim = dim3(256, 1, 1);
        cfg.dynamicSmemBytes = dsmem;
        cfg.attrs = attr;
        cfg.numAttrs = 1;
        cudaLaunchKernelEx(&cfg, infonce_mma_kernel);
    }

    // finalize with programmatic dependent launch on main
    {
        cudaLaunchAttribute attr[1];
        attr[0].id = cudaLaunchAttributeProgrammaticStreamSerialization;
        attr[0].val.programmaticStreamSerializationAllowed = 1;
        cudaLaunchConfig_t cfg = {};
        cfg.gridDim = dim3(32, 1, 1);
        cfg.blockDim = dim3(256, 1, 1);
        cfg.dynamicSmemBytes = 0;
        cfg.attrs = attr;
        cfg.numAttrs = 1;
        cudaLaunchKernelEx(&cfg, finalize_kernel, (float*)d_out);
    }
}